// round 4
// baseline (speedup 1.0000x reference)
#include <cuda_runtime.h>
#include <cstdint>

// DistMult forward scoring:
//   score[e] = sum_d h[src[e],d] * fwd_rel[etype[e],d] * h[dst[e],d]
// E = 640000, D = 128. Index arrays are int32 on device (JAX x64 disabled).
//
// R4: cache-policy split.
//  - h gathers (5.1 MB, ~zero L1 temporal reuse) -> __ldcg: L2-only, do not
//    allocate in L1. Stops h from thrashing L1.
//  - fwd_rel (256 KB ~= L1 capacity, ~8.6 refs/row/SM) -> default cached load,
//    now stays L1-resident -> rel's 512 B/edge drops out of L2 traffic.
//  L2 bytes/edge: ~1536 -> ~1024 (-33%), and L2 is the binding pipe (65.8%).
//
// Layout: 8 lanes per edge, 4 edges per warp (keeps index/shfl/store overhead
// amortized; per LDG.128 each 8-lane group reads one contiguous 128B line).

#define EMB_DIM 128

__global__ __launch_bounds__(256) void distmult_score_kernel(
    const float* __restrict__ h,
    const int* __restrict__ src,
    const int* __restrict__ dst,
    const int* __restrict__ etype,
    const float* __restrict__ fwd_rel,
    float* __restrict__ out,
    int n_edges)
{
    const int warp_id = (blockIdx.x * blockDim.x + threadIdx.x) >> 5;
    const int lane    = threadIdx.x & 31;
    const int group   = lane >> 3;   // 0..3 : which edge within the warp
    const int sl      = lane & 7;    // 0..7 : sub-lane within the edge group

    int e = warp_id * 4 + group;
    const bool valid = (e < n_edges);
    if (e >= n_edges) e = n_edges - 1;   // clamp; keep all lanes convergent

    // 4 distinct addresses per warp, 16B span -> 1 wavefront per array.
    const int s = src[e];
    const int d = dst[e];
    const int t = etype[e];

    const float4* __restrict__ hu = reinterpret_cast<const float4*>(h + (size_t)s * EMB_DIM);
    const float4* __restrict__ hv = reinterpret_cast<const float4*>(h + (size_t)d * EMB_DIM);
    const float4* __restrict__ wr = reinterpret_cast<const float4*>(fwd_rel + (size_t)t * EMB_DIM);

    // h: .cg (L2-only). rel: default (L1-cached, stays resident).
    float4 a0 = __ldcg(hu + sl);
    float4 a1 = __ldcg(hu + sl + 8);
    float4 a2 = __ldcg(hu + sl + 16);
    float4 a3 = __ldcg(hu + sl + 24);
    float4 c0 = __ldcg(hv + sl);
    float4 c1 = __ldcg(hv + sl + 8);
    float4 c2 = __ldcg(hv + sl + 16);
    float4 c3 = __ldcg(hv + sl + 24);
    float4 b0 = __ldg(wr + sl);
    float4 b1 = __ldg(wr + sl + 8);
    float4 b2 = __ldg(wr + sl + 16);
    float4 b3 = __ldg(wr + sl + 24);

    float acc0 = a0.x * b0.x * c0.x;
    acc0 = fmaf(a0.y * b0.y, c0.y, acc0);
    acc0 = fmaf(a0.z * b0.z, c0.z, acc0);
    acc0 = fmaf(a0.w * b0.w, c0.w, acc0);

    float acc1 = a1.x * b1.x * c1.x;
    acc1 = fmaf(a1.y * b1.y, c1.y, acc1);
    acc1 = fmaf(a1.z * b1.z, c1.z, acc1);
    acc1 = fmaf(a1.w * b1.w, c1.w, acc1);

    float acc2 = a2.x * b2.x * c2.x;
    acc2 = fmaf(a2.y * b2.y, c2.y, acc2);
    acc2 = fmaf(a2.z * b2.z, c2.z, acc2);
    acc2 = fmaf(a2.w * b2.w, c2.w, acc2);

    float acc3 = a3.x * b3.x * c3.x;
    acc3 = fmaf(a3.y * b3.y, c3.y, acc3);
    acc3 = fmaf(a3.z * b3.z, c3.z, acc3);
    acc3 = fmaf(a3.w * b3.w, c3.w, acc3);

    float acc = (acc0 + acc1) + (acc2 + acc3);

    // Reduce across the 8 sub-lanes of each group (3 shuffles, all 4 edges at once).
    acc += __shfl_xor_sync(0xffffffffu, acc, 4);
    acc += __shfl_xor_sync(0xffffffffu, acc, 2);
    acc += __shfl_xor_sync(0xffffffffu, acc, 1);

    // Lanes 0,8,16,24 write out[e0..e3] -> contiguous 16B, 1 wavefront.
    if (valid && sl == 0) out[e] = acc;
}

extern "C" void kernel_launch(void* const* d_in, const int* in_sizes, int n_in,
                              void* d_out, int out_size)
{
    const float* h       = (const float*)d_in[0];
    const int*   src     = (const int*)d_in[1];
    const int*   dst     = (const int*)d_in[2];
    const int*   etype   = (const int*)d_in[3];
    const float* fwd_rel = (const float*)d_in[4];
    // d_in[5] = rev_rel, unused in forward scoring.
    float* out = (float*)d_out;

    const int n_edges = in_sizes[1];               // src element count
    const int threads = 256;                       // 8 warps -> 32 edges per block
    const int edges_per_block = (threads / 32) * 4;
    const int blocks  = (n_edges + edges_per_block - 1) / edges_per_block;

    distmult_score_kernel<<<blocks, threads>>>(h, src, dst, etype, fwd_rel,
                                               out, n_edges);
}

// round 5
// speedup vs baseline: 1.1349x; 1.1349x over previous
#include <cuda_runtime.h>
#include <cstdint>

// DistMult forward scoring:
//   score[e] = sum_d h[src[e],d] * fwd_rel[etype[e],d] * h[dst[e],d]
// E = 640000, D = 128. Index arrays are int32 on device (JAX x64 disabled).
//
// R5: occupancy push. R4's .cg experiment showed the kernel is L1tex-
// wavefront/latency bound (not L2-BW bound): ~52 L1 wavefronts per warp,
// 1080 warps/SM -> ~31us floor, and we run at ~58% of it. Fix: force
// regs<=32 via __launch_bounds__(256, 8) and structure loads as a 4-step
// unrolled loop (3 loads + FMAs per step, ~3 float4 live) so the SM holds
// ~64 warps and keeps the L1 queue continuously fed.
//
// Layout: 8 lanes per edge, 4 edges per warp (index/shfl/store overhead
// amortized 4x; per LDG.128 each 8-lane group reads one contiguous 128B line).

#define EMB_DIM 128

__global__ __launch_bounds__(256, 8) void distmult_score_kernel(
    const float* __restrict__ h,
    const int* __restrict__ src,
    const int* __restrict__ dst,
    const int* __restrict__ etype,
    const float* __restrict__ fwd_rel,
    float* __restrict__ out,
    int n_edges)
{
    const int warp_id = (blockIdx.x * blockDim.x + threadIdx.x) >> 5;
    const int lane    = threadIdx.x & 31;
    const int group   = lane >> 3;   // 0..3 : which edge within the warp
    const int sl      = lane & 7;    // 0..7 : sub-lane within the edge group

    int e = warp_id * 4 + group;
    const bool valid = (e < n_edges);
    if (e >= n_edges) e = n_edges - 1;   // clamp; keep all lanes convergent

    // 4 distinct addresses per warp, 16B span -> 1 wavefront per array.
    const int s = src[e];
    const int d = dst[e];
    const int t = etype[e];

    const float4* __restrict__ hu = reinterpret_cast<const float4*>(h + (size_t)s * EMB_DIM);
    const float4* __restrict__ hv = reinterpret_cast<const float4*>(h + (size_t)d * EMB_DIM);
    const float4* __restrict__ wr = reinterpret_cast<const float4*>(fwd_rel + (size_t)t * EMB_DIM);

    float acc = 0.0f;
    #pragma unroll
    for (int j = 0; j < 4; j++) {
        const int idx = sl + j * 8;
        const float4 a = hu[idx];
        const float4 b = wr[idx];
        const float4 c = hv[idx];
        float p = a.x * b.x * c.x;
        p = fmaf(a.y * b.y, c.y, p);
        p = fmaf(a.z * b.z, c.z, p);
        p = fmaf(a.w * b.w, c.w, p);
        acc += p;
    }

    // Reduce across the 8 sub-lanes of each group (3 shuffles, all 4 edges at once).
    acc += __shfl_xor_sync(0xffffffffu, acc, 4);
    acc += __shfl_xor_sync(0xffffffffu, acc, 2);
    acc += __shfl_xor_sync(0xffffffffu, acc, 1);

    // Lanes 0,8,16,24 write out[e0..e3] -> contiguous 16B, 1 wavefront.
    if (valid && sl == 0) out[e] = acc;
}

extern "C" void kernel_launch(void* const* d_in, const int* in_sizes, int n_in,
                              void* d_out, int out_size)
{
    const float* h       = (const float*)d_in[0];
    const int*   src     = (const int*)d_in[1];
    const int*   dst     = (const int*)d_in[2];
    const int*   etype   = (const int*)d_in[3];
    const float* fwd_rel = (const float*)d_in[4];
    // d_in[5] = rev_rel, unused in forward scoring.
    float* out = (float*)d_out;

    const int n_edges = in_sizes[1];               // src element count
    const int threads = 256;                       // 8 warps -> 32 edges per block
    const int edges_per_block = (threads / 32) * 4;
    const int blocks  = (n_edges + edges_per_block - 1) / edges_per_block;

    distmult_score_kernel<<<blocks, threads>>>(h, src, dst, etype, fwd_rel,
                                               out, n_edges);
}

// round 6
// speedup vs baseline: 1.1625x; 1.0243x over previous
#include <cuda_runtime.h>
#include <cstdint>

// DistMult forward scoring:
//   score[e] = sum_d h[src[e],d] * fwd_rel[etype[e],d] * h[dst[e],d]
// E = 640000, D = 128. Index arrays are int32 on device (JAX x64 disabled).
//
// R6 = R5 (high-occupancy loop structure, regs=32, occ 86%) + cache-policy
// split retried at high occupancy:
//   - h gathers -> __ldcg (L2-only). h L1 hit rate is ~4% anyway (5.1 MB
//     random-gathered vs 228 KB L1); bypassing stops h evicting rel.
//   - fwd_rel -> __ldg (L1-allocating). 256 KB, ~8.6 refs/row/SM -> high L1
//     hit rate once h stops thrashing. Cuts ~1/3 of L2 traffic and the
//     L2-fill bubbles that hold L1 wavefront issue at 70%.
//
// Layout: 8 lanes per edge, 4 edges per warp (per LDG.128 each 8-lane group
// reads one full contiguous 128B line; index/shfl/store overhead amortized 4x).

#define EMB_DIM 128

__global__ __launch_bounds__(256, 8) void distmult_score_kernel(
    const float* __restrict__ h,
    const int* __restrict__ src,
    const int* __restrict__ dst,
    const int* __restrict__ etype,
    const float* __restrict__ fwd_rel,
    float* __restrict__ out,
    int n_edges)
{
    const int warp_id = (blockIdx.x * blockDim.x + threadIdx.x) >> 5;
    const int lane    = threadIdx.x & 31;
    const int group   = lane >> 3;   // 0..3 : which edge within the warp
    const int sl      = lane & 7;    // 0..7 : sub-lane within the edge group

    int e = warp_id * 4 + group;
    const bool valid = (e < n_edges);
    if (e >= n_edges) e = n_edges - 1;   // clamp; keep all lanes convergent

    // 4 distinct addresses per warp, 16B span -> 1 wavefront per array.
    const int s = src[e];
    const int d = dst[e];
    const int t = etype[e];

    const float4* __restrict__ hu = reinterpret_cast<const float4*>(h + (size_t)s * EMB_DIM);
    const float4* __restrict__ hv = reinterpret_cast<const float4*>(h + (size_t)d * EMB_DIM);
    const float4* __restrict__ wr = reinterpret_cast<const float4*>(fwd_rel + (size_t)t * EMB_DIM);

    float acc = 0.0f;
    #pragma unroll
    for (int j = 0; j < 4; j++) {
        const int idx = sl + j * 8;
        const float4 a = __ldcg(hu + idx);   // h: L2-only
        const float4 c = __ldcg(hv + idx);   // h: L2-only
        const float4 b = __ldg(wr + idx);    // rel: L1-resident
        float p = a.x * b.x * c.x;
        p = fmaf(a.y * b.y, c.y, p);
        p = fmaf(a.z * b.z, c.z, p);
        p = fmaf(a.w * b.w, c.w, p);
        acc += p;
    }

    // Reduce across the 8 sub-lanes of each group (3 shuffles, all 4 edges at once).
    acc += __shfl_xor_sync(0xffffffffu, acc, 4);
    acc += __shfl_xor_sync(0xffffffffu, acc, 2);
    acc += __shfl_xor_sync(0xffffffffu, acc, 1);

    // Lanes 0,8,16,24 write out[e0..e3] -> contiguous 16B, 1 wavefront.
    if (valid && sl == 0) out[e] = acc;
}

extern "C" void kernel_launch(void* const* d_in, const int* in_sizes, int n_in,
                              void* d_out, int out_size)
{
    const float* h       = (const float*)d_in[0];
    const int*   src     = (const int*)d_in[1];
    const int*   dst     = (const int*)d_in[2];
    const int*   etype   = (const int*)d_in[3];
    const float* fwd_rel = (const float*)d_in[4];
    // d_in[5] = rev_rel, unused in forward scoring.
    float* out = (float*)d_out;

    const int n_edges = in_sizes[1];               // src element count
    const int threads = 256;                       // 8 warps -> 32 edges per block
    const int edges_per_block = (threads / 32) * 4;
    const int blocks  = (n_edges + edges_per_block - 1) / edges_per_block;

    distmult_score_kernel<<<blocks, threads>>>(h, src, dst, etype, fwd_rel,
                                               out, n_edges);
}